// round 8
// baseline (speedup 1.0000x reference)
#include <cuda_runtime.h>
#include <math.h>
#include <stdint.h>

// Problem constants
#define B_SZ     4
#define SEQ_LEN  2048
#define D_MODEL  256
#define D_INNER  512
#define D_STATE  16
#define KCONV    4
#define DT_RANK  16
#define N_CLS    10
#define BL       (B_SZ * SEQ_LEN)          // 8192
#define XPROJ_N  (DT_RANK + 2 * D_STATE)   // 48
#define SEGS     16
#define SEG_LEN  (SEQ_LEN / SEGS)          // 128

// Scratch (device globals; no allocation allowed)
__device__ float g_xz[BL * 2 * D_INNER];     // (8192, 1024) : u_raw | silu(z)
__device__ float g_uc[BL * D_INNER];         // (8192, 512)  : conv+silu output
__device__ float g_xdbl[BL * XPROJ_N];       // (8192, 48)   : dt_raw | Bp | Cp
__device__ float g_pooled[B_SZ * D_INNER];   // (4, 512)
// Segment-scan summaries, packed: [b][seg][d][n] -> {locAcc, coef, Aprod, hend}
__device__ float4 g_seg[B_SZ * SEGS * D_INNER * D_STATE];
__device__ float  g_accD[B_SZ * SEGS * D_INNER];

// ---------------------------------------------------------------------------
// tf32 helpers
// ---------------------------------------------------------------------------
__device__ __forceinline__ uint32_t f2tf32(float f) {
    uint32_t r;
    asm("cvt.rna.tf32.f32 %0, %1;" : "=r"(r) : "f"(f));
    return r;
}

__device__ __forceinline__ void split_tf32(float v, uint32_t& hi, uint32_t& lo) {
    hi = f2tf32(v);
    lo = f2tf32(v - __uint_as_float(hi));
}

__device__ __forceinline__ void mma_tf32(float& c0, float& c1, float& c2, float& c3,
                                         uint32_t a0, uint32_t a1, uint32_t a2, uint32_t a3,
                                         uint32_t b0, uint32_t b1) {
    asm("mma.sync.aligned.m16n8k8.row.col.f32.tf32.tf32.f32 "
        "{%0,%1,%2,%3},{%4,%5,%6,%7},{%8,%9},{%0,%1,%2,%3};"
        : "+f"(c0), "+f"(c1), "+f"(c2), "+f"(c3)
        : "r"(a0), "r"(a1), "r"(a2), "r"(a3), "r"(b0), "r"(b1));
}

// ---------------------------------------------------------------------------
// K1: xz = x @ W_in  (8192 x 1024, K=256), tf32 tensor cores (single pass).
// z-half columns (>=512) get silu applied in the epilogue.
// ---------------------------------------------------------------------------
__global__ __launch_bounds__(256) void gemm1_tc_kernel(const float* __restrict__ A,
                                                       const float* __restrict__ Bm) {
    constexpr int N = 2 * D_INNER, K = D_MODEL;
    constexpr int BM = 128, BN = 128, BK = 16;
    constexpr int NCHUNK = K / BK;                 // 16
    constexpr int ASTR = BK + 4;                   // 20
    constexpr int BSTR = BN + 8;                   // 136
    __shared__ uint32_t As[2][BM][ASTR];
    __shared__ uint32_t Bs[2][BK][BSTR];

    const int tid  = threadIdx.x;
    const int warp = tid >> 5, lane = tid & 31;
    const int wm = warp & 1, wn = warp >> 1;       // 2 x 4 warp grid
    const int gid = lane >> 2, tig = lane & 3;

    const float* Ab = A + (size_t)blockIdx.y * BM * K;
    const float* Bb = Bm + blockIdx.x * BN;

    const int a_r0 = tid >> 2, a_c4 = (tid & 3) << 2;
    const int b_r0 = tid >> 5, b_c4 = (tid & 31) << 2;

    float acc[4][4][4];
#pragma unroll
    for (int mi = 0; mi < 4; mi++)
#pragma unroll
        for (int ni = 0; ni < 4; ni++)
#pragma unroll
            for (int q = 0; q < 4; q++) acc[mi][ni][q] = 0.f;

    float4 pa[2], pb[2];
    pa[0] = *(const float4*)(Ab + a_r0 * K + a_c4);
    pa[1] = *(const float4*)(Ab + (a_r0 + 64) * K + a_c4);
    pb[0] = *(const float4*)(Bb + b_r0 * N + b_c4);
    pb[1] = *(const float4*)(Bb + (b_r0 + 8) * N + b_c4);
#pragma unroll
    for (int i = 0; i < 2; i++) {
        const int ar = a_r0 + i * 64;
        As[0][ar][a_c4 + 0] = f2tf32(pa[i].x); As[0][ar][a_c4 + 1] = f2tf32(pa[i].y);
        As[0][ar][a_c4 + 2] = f2tf32(pa[i].z); As[0][ar][a_c4 + 3] = f2tf32(pa[i].w);
        const int br = b_r0 + i * 8;
        Bs[0][br][b_c4 + 0] = f2tf32(pb[i].x); Bs[0][br][b_c4 + 1] = f2tf32(pb[i].y);
        Bs[0][br][b_c4 + 2] = f2tf32(pb[i].z); Bs[0][br][b_c4 + 3] = f2tf32(pb[i].w);
    }
    __syncthreads();

    int buf = 0;
    for (int c = 0; c < NCHUNK; c++) {
        if (c + 1 < NCHUNK) {
            const int k0 = (c + 1) * BK;
            pa[0] = *(const float4*)(Ab + a_r0 * K + k0 + a_c4);
            pa[1] = *(const float4*)(Ab + (a_r0 + 64) * K + k0 + a_c4);
            pb[0] = *(const float4*)(Bb + (k0 + b_r0) * N + b_c4);
            pb[1] = *(const float4*)(Bb + (k0 + b_r0 + 8) * N + b_c4);
        }
#pragma unroll
        for (int ks = 0; ks < BK; ks += 8) {
            uint32_t af[4][4], bf[4][2];
#pragma unroll
            for (int mi = 0; mi < 4; mi++) {
                const int r = wm * 64 + mi * 16 + gid;
                af[mi][0] = As[buf][r][ks + tig];
                af[mi][1] = As[buf][r + 8][ks + tig];
                af[mi][2] = As[buf][r][ks + tig + 4];
                af[mi][3] = As[buf][r + 8][ks + tig + 4];
            }
#pragma unroll
            for (int ni = 0; ni < 4; ni++) {
                const int cc = wn * 32 + ni * 8 + gid;
                bf[ni][0] = Bs[buf][ks + tig][cc];
                bf[ni][1] = Bs[buf][ks + tig + 4][cc];
            }
#pragma unroll
            for (int mi = 0; mi < 4; mi++)
#pragma unroll
                for (int ni = 0; ni < 4; ni++)
                    mma_tf32(acc[mi][ni][0], acc[mi][ni][1], acc[mi][ni][2], acc[mi][ni][3],
                             af[mi][0], af[mi][1], af[mi][2], af[mi][3],
                             bf[ni][0], bf[ni][1]);
        }
        if (c + 1 < NCHUNK) {
            const int nb = buf ^ 1;
#pragma unroll
            for (int i = 0; i < 2; i++) {
                const int ar = a_r0 + i * 64;
                As[nb][ar][a_c4 + 0] = f2tf32(pa[i].x); As[nb][ar][a_c4 + 1] = f2tf32(pa[i].y);
                As[nb][ar][a_c4 + 2] = f2tf32(pa[i].z); As[nb][ar][a_c4 + 3] = f2tf32(pa[i].w);
                const int br = b_r0 + i * 8;
                Bs[nb][br][b_c4 + 0] = f2tf32(pb[i].x); Bs[nb][br][b_c4 + 1] = f2tf32(pb[i].y);
                Bs[nb][br][b_c4 + 2] = f2tf32(pb[i].z); Bs[nb][br][b_c4 + 3] = f2tf32(pb[i].w);
            }
            __syncthreads();
            buf ^= 1;
        }
    }

    const bool is_z = (blockIdx.x >= (D_INNER / BN));
    float* Cb = g_xz + (size_t)blockIdx.y * BM * N + blockIdx.x * BN;
#pragma unroll
    for (int mi = 0; mi < 4; mi++) {
#pragma unroll
        for (int ni = 0; ni < 4; ni++) {
            const int row = wm * 64 + mi * 16 + gid;
            const int col = wn * 32 + ni * 8 + 2 * tig;
            float v0 = acc[mi][ni][0], v1 = acc[mi][ni][1];
            float v2 = acc[mi][ni][2], v3 = acc[mi][ni][3];
            if (is_z) {
                v0 = v0 * __frcp_rn(1.0f + __expf(-v0));
                v1 = v1 * __frcp_rn(1.0f + __expf(-v1));
                v2 = v2 * __frcp_rn(1.0f + __expf(-v2));
                v3 = v3 * __frcp_rn(1.0f + __expf(-v3));
            }
            *(float2*)(Cb + (size_t)row * N + col) = make_float2(v0, v1);
            *(float2*)(Cb + (size_t)(row + 8) * N + col) = make_float2(v2, v3);
        }
    }
}

// ---------------------------------------------------------------------------
// K2: fused conv+silu+xproj. Per block: 32 (b,l) rows.
//   - stage raw u (xz u-half) rows with 3-row causal halo
//   - conv(K=4)+bias+silu in fp32 -> u_s tile; also STG to g_uc (for scan)
//   - TC GEMM (3-pass split-tf32) u_c @ W_xproj -> g_xdbl
// ---------------------------------------------------------------------------
__global__ __launch_bounds__(256) void xproj_fused_kernel(const float* __restrict__ W,
                                                          const float* __restrict__ W_conv,
                                                          const float* __restrict__ b_conv) {
    constexpr int K = D_INNER;          // 512
    constexpr int BM = 32, BN = 64, BK = 16;
    constexpr int NCHUNK = K / BK;      // 32
    constexpr int ASTR = BK + 4;        // 20
    constexpr int BSTR = BN + 8;        // 72
    constexpr int HR = BM + KCONV - 1;  // 35 raw rows

    __shared__ float raw_s[HR][BK];     // 35 x 16
    __shared__ float u_s[BM][ASTR];     // conv output tile
    __shared__ float Bs[BK][BSTR];
    __shared__ float Wc_s[D_INNER][KCONV];   // 8 KB
    __shared__ float bc_s[D_INNER];          // 2 KB

    const int tid  = threadIdx.x;
    const int warp = tid >> 5, lane = tid & 31;
    const int wm = warp & 1, wn = warp >> 1;     // 2 x 4 warps, tile 16 x 16
    const int gid = lane >> 2, tig = lane & 3;

    const int row0 = blockIdx.x * BM;            // global bl
    const int l0   = row0 & (SEQ_LEN - 1);       // l within batch

    // stage conv weights/bias once
    for (int i = tid; i < D_INNER * KCONV; i += 256)
        Wc_s[i >> 2][i & 3] = W_conv[i];
    for (int i = tid; i < D_INNER; i += 256)
        bc_s[i] = b_conv[i];

    float acc[2][4];
#pragma unroll
    for (int ni = 0; ni < 2; ni++)
#pragma unroll
        for (int q = 0; q < 4; q++) acc[ni][q] = 0.f;

    for (int c = 0; c < NCHUNK; c++) {
        const int k0 = c * BK;
        __syncthreads();   // prev MMA done reading u_s/Bs; Wc_s ready (c==0)
        // load raw u rows [row0-3 .. row0+31] x 16 cols (zero-pad l<0)
        for (int i = tid; i < HR * BK; i += 256) {
            const int r = i >> 4, cc = i & 15;
            const int lg = l0 - (KCONV - 1) + r;
            raw_s[r][cc] = (lg >= 0)
                ? g_xz[(size_t)(row0 - (KCONV - 1) + r) * (2 * D_INNER) + k0 + cc]
                : 0.f;
        }
        // load W_xproj chunk (zero-pad n>=48)
#pragma unroll
        for (int s = 0; s < 4; s++) {
            const int i = tid + s * 256;
            const int kk = i >> 6, nn = i & 63;
            Bs[kk][nn] = (nn < XPROJ_N) ? W[(size_t)(k0 + kk) * XPROJ_N + nn] : 0.f;
        }
        __syncthreads();
        // conv + bias + silu -> u_s ; also write g_uc
#pragma unroll
        for (int s = 0; s < 2; s++) {
            const int i = tid + s * 256;
            const int r = i >> 4, cc = i & 15;
            float v = bc_s[k0 + cc];
#pragma unroll
            for (int t = 0; t < KCONV; t++)
                v = fmaf(raw_s[r + t][cc], Wc_s[k0 + cc][t], v);
            v = v * __frcp_rn(1.0f + __expf(-v));
            u_s[r][cc] = v;
            g_uc[(size_t)(row0 + r) * D_INNER + k0 + cc] = v;
        }
        __syncthreads();
        // TC GEMM on this K-chunk (3-pass split-tf32)
#pragma unroll
        for (int ks = 0; ks < BK; ks += 8) {
            uint32_t ahi[4], alo[4], bhi[2][2], blo[2][2];
            const int r = wm * 16 + gid;
            split_tf32(u_s[r][ks + tig],         ahi[0], alo[0]);
            split_tf32(u_s[r + 8][ks + tig],     ahi[1], alo[1]);
            split_tf32(u_s[r][ks + tig + 4],     ahi[2], alo[2]);
            split_tf32(u_s[r + 8][ks + tig + 4], ahi[3], alo[3]);
#pragma unroll
            for (int ni = 0; ni < 2; ni++) {
                const int cc = wn * 16 + ni * 8 + gid;
                split_tf32(Bs[ks + tig][cc],     bhi[ni][0], blo[ni][0]);
                split_tf32(Bs[ks + tig + 4][cc], bhi[ni][1], blo[ni][1]);
            }
#pragma unroll
            for (int ni = 0; ni < 2; ni++) {
                mma_tf32(acc[ni][0], acc[ni][1], acc[ni][2], acc[ni][3],
                         ahi[0], ahi[1], ahi[2], ahi[3], bhi[ni][0], bhi[ni][1]);
                mma_tf32(acc[ni][0], acc[ni][1], acc[ni][2], acc[ni][3],
                         alo[0], alo[1], alo[2], alo[3], bhi[ni][0], bhi[ni][1]);
                mma_tf32(acc[ni][0], acc[ni][1], acc[ni][2], acc[ni][3],
                         ahi[0], ahi[1], ahi[2], ahi[3], blo[ni][0], blo[ni][1]);
            }
        }
    }

#pragma unroll
    for (int ni = 0; ni < 2; ni++) {
        const int row = wm * 16 + gid;
        const int col = wn * 16 + ni * 8 + 2 * tig;
        if (col < XPROJ_N) {
            *(float2*)(g_xdbl + (size_t)(row0 + row) * XPROJ_N + col) =
                make_float2(acc[ni][0], acc[ni][1]);
            *(float2*)(g_xdbl + (size_t)(row0 + row + 8) * XPROJ_N + col) =
                make_float2(acc[ni][2], acc[ni][3]);
        }
    }
}

// ---------------------------------------------------------------------------
// K3: SEGMENTED selective scan. Each block: one (b, seg, 16-d group);
// 256 threads = 16 d x 16 n. CH=64 chunking (fewer syncs).
// ---------------------------------------------------------------------------
__global__ __launch_bounds__(256) void scan_seg_kernel(const float* __restrict__ A_log,
                                                       const float* __restrict__ W_dt,
                                                       const float* __restrict__ b_dt) {
    constexpr int CH = 64;
    constexpr int PW = 68;
    __shared__ float w_s[16][PW];     // dt           [dd][li]
    __shared__ float wu_s[16][PW];    // dt*u (phase1: u)
    __shared__ float g_s[16][PW];     // gate
    __shared__ float bp_s[16][PW];    // Bp transposed [n][li]
    __shared__ float cp_s[16][PW];    // Cp transposed [n][li]
    __shared__ float xd_s[CH * XPROJ_N];   // 12 KB
    __shared__ float Wdt_s[DT_RANK][16];
    __shared__ float bdt_s[16];
    __shared__ float accD_red[16][16];

    const int tid = threadIdx.x;
    const int gi = tid >> 4;       // d channel within block
    const int n  = tid & 15;       // state index
    const int blk  = blockIdx.x;
    const int dgrp = blk & 31;
    const int s    = (blk >> 5) & (SEGS - 1);
    const int b    = blk >> 9;
    const int d0 = dgrp * 16;
    const int d  = d0 + gi;
    const int l_base = s * SEG_LEN;

    const int p_dd = tid & 15;
    const int p_li = tid >> 4;

    if (tid < DT_RANK * 16)
        Wdt_s[tid >> 4][tid & 15] = W_dt[(tid >> 4) * D_INNER + d0 + (tid & 15)];
    if (tid < 16) bdt_s[tid] = b_dt[d0 + tid];

    const float A_n = -__expf(A_log[d * D_STATE + n]);

    float h = 0.f, P = 1.f, acc = 0.f, coef = 0.f, accD_th = 0.f;

    for (int l0 = l_base; l0 < l_base + SEG_LEN; l0 += CH) {
        __syncthreads();
        const size_t bl0 = (size_t)(b * SEQ_LEN + l0);
        // phase 1: cooperative loads (gate pre-silu'd by GEMM epilogue)
        {
            const int dd = tid & 15, li0 = tid >> 4;
#pragma unroll
            for (int q = 0; q < 4; q++) {
                const int li = li0 + q * 16;
                const size_t bl = bl0 + li;
                wu_s[dd][li] = g_uc[bl * D_INNER + d0 + dd];                  // u
                g_s[dd][li]  = g_xz[bl * (2 * D_INNER) + D_INNER + d0 + dd];  // gate
            }
        }
#pragma unroll
        for (int q = 0; q < 12; q++) {
            const int i = tid + q * 256;
            xd_s[i] = g_xdbl[bl0 * XPROJ_N + i];
        }
        __syncthreads();
        // phase 2: dt = softplus(xd.W_dt + b); wu = dt*u; accD += gate*u;
        // plus Bp/Cp transpose into [n][li] layout.
#pragma unroll
        for (int q = 0; q < 4; q++) {
            const int li = p_li + q * 16;
            float dtr = bdt_s[p_dd];
#pragma unroll
            for (int r = 0; r < DT_RANK; r++)
                dtr = fmaf(xd_s[li * XPROJ_N + r], Wdt_s[r][p_dd], dtr);
            const float w = (dtr > 15.0f) ? dtr : log1pf(__expf(dtr));
            const float u = wu_s[p_dd][li];
            const float gate = g_s[p_dd][li];
            w_s[p_dd][li]  = w;
            wu_s[p_dd][li] = w * u;
            accD_th = fmaf(gate, u, accD_th);
            bp_s[p_dd][li] = xd_s[li * XPROJ_N + DT_RANK + p_dd];
            cp_s[p_dd][li] = xd_s[li * XPROJ_N + DT_RANK + D_STATE + p_dd];
        }
        __syncthreads();
        // phase 3: serial scan over the chunk
#pragma unroll
        for (int l4 = 0; l4 < CH; l4 += 4) {
            const float4 w4  = *(const float4*)&w_s[gi][l4];
            const float4 wu4 = *(const float4*)&wu_s[gi][l4];
            const float4 g4  = *(const float4*)&g_s[gi][l4];
            const float4 bp4 = *(const float4*)&bp_s[n][l4];
            const float4 cp4 = *(const float4*)&cp_s[n][l4];
#pragma unroll
            for (int q = 0; q < 4; q++) {
                const float w  = (q == 0) ? w4.x  : (q == 1) ? w4.y  : (q == 2) ? w4.z  : w4.w;
                const float wu = (q == 0) ? wu4.x : (q == 1) ? wu4.y : (q == 2) ? wu4.z : wu4.w;
                const float gt = (q == 0) ? g4.x  : (q == 1) ? g4.y  : (q == 2) ? g4.z  : g4.w;
                const float bn = (q == 0) ? bp4.x : (q == 1) ? bp4.y : (q == 2) ? bp4.z : bp4.w;
                const float cn = (q == 0) ? cp4.x : (q == 1) ? cp4.y : (q == 2) ? cp4.z : cp4.w;
                const float dA = __expf(w * A_n);
                P *= dA;
                h = fmaf(dA, h, wu * bn);
                const float gc = gt * cn;
                acc  = fmaf(gc, h, acc);
                coef = fmaf(gc, P, coef);
            }
        }
    }
    // write packed segment summary (coalesced: tid -> consecutive [d][n])
    const size_t base = ((size_t)(b * SEGS + s) * D_INNER + d0) * D_STATE + tid;
    g_seg[base] = make_float4(acc, coef, P, h);
    // accD reduction over the 16 li-threads per dd
    accD_red[p_li][p_dd] = accD_th;
    __syncthreads();
    if (n == 0) {
        float accD = 0.f;
#pragma unroll
        for (int g = 0; g < 16; g++) accD += accD_red[g][gi];
        g_accD[(size_t)(b * SEGS + s) * D_INNER + d] = accD;
    }
}

// ---------------------------------------------------------------------------
// K4: fixup — combine SEGS segment summaries per chain, reduce over n,
// apply D-skip, write pooled mean.
// ---------------------------------------------------------------------------
__global__ __launch_bounds__(256) void scan_fix_kernel(const float* __restrict__ Dp) {
    const int idx = blockIdx.x * 256 + threadIdx.x;     // over 4*512*16
    const int n = idx & 15;
    const int d = (idx >> 4) & (D_INNER - 1);
    const int b = idx >> 13;

    float carry = 0.f, accT = 0.f, accD = 0.f;
#pragma unroll
    for (int s = 0; s < SEGS; s++) {
        const float4 sg = g_seg[((size_t)(b * SEGS + s) * D_INNER + d) * D_STATE + n];
        accT  = accT + sg.x + sg.y * carry;      // locAcc + coef*carry
        carry = fmaf(sg.z, carry, sg.w);         // Aprod*carry + hend
        if (n == 0) accD += g_accD[(size_t)(b * SEGS + s) * D_INNER + d];
    }
#pragma unroll
    for (int off = 8; off >= 1; off >>= 1)
        accT += __shfl_xor_sync(0xffffffffu, accT, off);
    if (n == 0)
        g_pooled[b * D_INNER + d] = (accT + Dp[d] * accD) * (1.0f / SEQ_LEN);
}

// ---------------------------------------------------------------------------
// K5: logits = (pooled @ W_out) @ W_cls + b_cls   (tiny)
// ---------------------------------------------------------------------------
__global__ __launch_bounds__(256) void final_kernel(const float* __restrict__ W_out,
                                                    const float* __restrict__ W_cls,
                                                    const float* __restrict__ b_cls,
                                                    float* __restrict__ out) {
    __shared__ float p_s[B_SZ * D_INNER];
    __shared__ float t_s[B_SZ * D_MODEL];
    const int tid = threadIdx.x;
    for (int i = tid; i < B_SZ * D_INNER; i += 256) p_s[i] = g_pooled[i];
    __syncthreads();
    float a0 = 0.f, a1 = 0.f, a2 = 0.f, a3 = 0.f;
    for (int k = 0; k < D_INNER; k++) {
        const float w = W_out[k * D_MODEL + tid];
        a0 = fmaf(p_s[k], w, a0);
        a1 = fmaf(p_s[D_INNER + k], w, a1);
        a2 = fmaf(p_s[2 * D_INNER + k], w, a2);
        a3 = fmaf(p_s[3 * D_INNER + k], w, a3);
    }
    t_s[tid] = a0; t_s[D_MODEL + tid] = a1;
    t_s[2 * D_MODEL + tid] = a2; t_s[3 * D_MODEL + tid] = a3;
    __syncthreads();
    if (tid < B_SZ * N_CLS) {
        const int bb = tid / N_CLS, c = tid % N_CLS;
        float acc = b_cls[c];
        for (int k = 0; k < D_MODEL; k++)
            acc = fmaf(t_s[bb * D_MODEL + k], W_cls[k * N_CLS + c], acc);
        out[tid] = acc;
    }
}

// ---------------------------------------------------------------------------
extern "C" void kernel_launch(void* const* d_in, const int* in_sizes, int n_in,
                              void* d_out, int out_size) {
    const float* x       = (const float*)d_in[0];
    const float* W_in    = (const float*)d_in[1];
    const float* W_conv  = (const float*)d_in[2];
    const float* b_conv  = (const float*)d_in[3];
    const float* W_xproj = (const float*)d_in[4];
    const float* W_dt    = (const float*)d_in[5];
    const float* b_dt    = (const float*)d_in[6];
    const float* A_log   = (const float*)d_in[7];
    const float* Dp      = (const float*)d_in[8];
    const float* W_out   = (const float*)d_in[9];
    const float* W_cls   = (const float*)d_in[10];
    const float* b_cls   = (const float*)d_in[11];
    float* out = (float*)d_out;

    gemm1_tc_kernel<<<dim3(2 * D_INNER / 128, BL / 128), 256>>>(x, W_in);
    xproj_fused_kernel<<<BL / 32, 256>>>(W_xproj, W_conv, b_conv);
    scan_seg_kernel<<<B_SZ * SEGS * (D_INNER / 16), 256>>>(A_log, W_dt, b_dt);
    scan_fix_kernel<<<B_SZ * D_INNER * D_STATE / 256, 256>>>(Dp);
    final_kernel<<<1, 256>>>(W_out, W_cls, b_cls, out);
}

// round 11
// speedup vs baseline: 1.1952x; 1.1952x over previous
#include <cuda_runtime.h>
#include <cuda_fp16.h>
#include <math.h>
#include <stdint.h>

// Problem constants
#define B_SZ     4
#define SEQ_LEN  2048
#define D_MODEL  256
#define D_INNER  512
#define D_STATE  16
#define KCONV    4
#define DT_RANK  16
#define N_CLS    10
#define BL       (B_SZ * SEQ_LEN)          // 8192
#define XPROJ_N  (DT_RANK + 2 * D_STATE)   // 48
#define SEGS     16
#define SEG_LEN  (SEQ_LEN / SEGS)          // 128

// Scratch (device globals; no allocation allowed)
__device__ float  g_xz[BL * 2 * D_INNER];    // (8192, 1024) : u_raw | silu(z)
__device__ float  g_uc[BL * D_INNER];        // (8192, 512)
__device__ float  g_xdbl[BL * XPROJ_N];      // (8192, 48)
__device__ float  g_pooled[B_SZ * D_INNER];
__device__ float4 g_seg[B_SZ * SEGS * D_INNER * D_STATE];
__device__ float  g_accD[B_SZ * SEGS * D_INNER];
__device__ __half g_x16[BL * D_MODEL];               // fp16 x            [8192][256]
__device__ __half g_w16T[2 * D_INNER * D_MODEL];     // fp16 W_in^T       [1024][256]

// ---------------------------------------------------------------------------
// mma helpers
// ---------------------------------------------------------------------------
__device__ __forceinline__ uint32_t f2tf32(float f) {
    uint32_t r;
    asm("cvt.rna.tf32.f32 %0, %1;" : "=r"(r) : "f"(f));
    return r;
}
__device__ __forceinline__ void split_tf32(float v, uint32_t& hi, uint32_t& lo) {
    hi = f2tf32(v);
    lo = f2tf32(v - __uint_as_float(hi));
}
__device__ __forceinline__ void mma_tf32(float& c0, float& c1, float& c2, float& c3,
                                         uint32_t a0, uint32_t a1, uint32_t a2, uint32_t a3,
                                         uint32_t b0, uint32_t b1) {
    asm("mma.sync.aligned.m16n8k8.row.col.f32.tf32.tf32.f32 "
        "{%0,%1,%2,%3},{%4,%5,%6,%7},{%8,%9},{%0,%1,%2,%3};"
        : "+f"(c0), "+f"(c1), "+f"(c2), "+f"(c3)
        : "r"(a0), "r"(a1), "r"(a2), "r"(a3), "r"(b0), "r"(b1));
}
__device__ __forceinline__ void mma_f16(float& c0, float& c1, float& c2, float& c3,
                                        uint32_t a0, uint32_t a1, uint32_t a2, uint32_t a3,
                                        uint32_t b0, uint32_t b1) {
    asm("mma.sync.aligned.m16n8k16.row.col.f32.f16.f16.f32 "
        "{%0,%1,%2,%3},{%4,%5,%6,%7},{%8,%9},{%0,%1,%2,%3};"
        : "+f"(c0), "+f"(c1), "+f"(c2), "+f"(c3)
        : "r"(a0), "r"(a1), "r"(a2), "r"(a3), "r"(b0), "r"(b1));
}

// ---------------------------------------------------------------------------
// K0a: x -> fp16
// ---------------------------------------------------------------------------
__global__ __launch_bounds__(256) void cvt_x_kernel(const float* __restrict__ x) {
    const int i = (blockIdx.x * 256 + threadIdx.x) * 4;
    float4 v = *(const float4*)(x + i);
    *(__half2*)(g_x16 + i) = __floats2half2_rn(v.x, v.y);
    *(__half2*)(g_x16 + i + 2) = __floats2half2_rn(v.z, v.w);
}

// ---------------------------------------------------------------------------
// K0b: W_in -> fp16 transposed  w16T[n][k] = W_in[k][n]
// ---------------------------------------------------------------------------
__global__ __launch_bounds__(256) void cvt_wT_kernel(const float* __restrict__ W_in) {
    __shared__ float t[32][33];
    const int tx = threadIdx.x & 31, ty = threadIdx.x >> 5;
    const int k0 = blockIdx.x * 32, n0 = blockIdx.y * 32;
#pragma unroll
    for (int j = 0; j < 4; j++)
        t[ty + j * 8][tx] = W_in[(size_t)(k0 + ty + j * 8) * (2 * D_INNER) + n0 + tx];
    __syncthreads();
#pragma unroll
    for (int j = 0; j < 4; j++)
        g_w16T[(size_t)(n0 + ty + j * 8) * D_MODEL + k0 + tx] =
            __float2half_rn(t[tx][ty + j * 8]);
}

// ---------------------------------------------------------------------------
// K1: xz = x @ W_in  (8192 x 1024, K=256), fp16 mma.sync.m16n8k16, fp32 accum.
// 128x128x32 block tile, 8 warps (2x4) of 64x32, double-buffered SMEM.
// z-half columns (blockIdx.x >= 4) get silu applied in the epilogue.
// ---------------------------------------------------------------------------
__global__ __launch_bounds__(256) void gemm1_f16_kernel() {
    constexpr int N = 2 * D_INNER, K = D_MODEL;
    constexpr int BM = 128, BN = 128, BK = 32;
    constexpr int NCHUNK = K / BK;                 // 8
    constexpr int STR = BK + 8;                    // 40 halves: conflict-free frag loads
    __shared__ __align__(16) __half As[2][BM][STR];
    __shared__ __align__(16) __half Bs[2][BN][STR];   // Bt: [n][k]

    const int tid  = threadIdx.x;
    const int warp = tid >> 5, lane = tid & 31;
    const int wm = warp & 1, wn = warp >> 1;       // 2 x 4 warp grid
    const int gid = lane >> 2, tig = lane & 3;

    const int row0 = blockIdx.y * BM;
    const int col0 = blockIdx.x * BN;
    const __half* Ag = g_x16 + (size_t)row0 * K;
    const __half* Bg = g_w16T + (size_t)col0 * K;

    // loaders: tile = 128 rows x 32 halves = 512 uint4; 2 per thread
    // u4 index i: r = i>>2, c8 = (i&3)*8
    const int i0 = tid * 2;
    const int l_r0 = i0 >> 2, l_c0 = (i0 & 3) * 8;
    const int l_r1 = (i0 + 1) >> 2, l_c1 = ((i0 + 1) & 3) * 8;

    float acc[4][4][4];
#pragma unroll
    for (int mi = 0; mi < 4; mi++)
#pragma unroll
        for (int ni = 0; ni < 4; ni++)
#pragma unroll
            for (int q = 0; q < 4; q++) acc[mi][ni][q] = 0.f;

    // prologue: chunk 0 -> buffer 0
    {
        uint4 a0v = *(const uint4*)(Ag + (size_t)l_r0 * K + l_c0);
        uint4 a1v = *(const uint4*)(Ag + (size_t)l_r1 * K + l_c1);
        uint4 b0v = *(const uint4*)(Bg + (size_t)l_r0 * K + l_c0);
        uint4 b1v = *(const uint4*)(Bg + (size_t)l_r1 * K + l_c1);
        *(uint4*)&As[0][l_r0][l_c0] = a0v;
        *(uint4*)&As[0][l_r1][l_c1] = a1v;
        *(uint4*)&Bs[0][l_r0][l_c0] = b0v;
        *(uint4*)&Bs[0][l_r1][l_c1] = b1v;
    }
    __syncthreads();

    int buf = 0;
    for (int c = 0; c < NCHUNK; c++) {
        uint4 pa0, pa1, pb0, pb1;
        if (c + 1 < NCHUNK) {
            const int k0 = (c + 1) * BK;
            pa0 = *(const uint4*)(Ag + (size_t)l_r0 * K + k0 + l_c0);
            pa1 = *(const uint4*)(Ag + (size_t)l_r1 * K + k0 + l_c1);
            pb0 = *(const uint4*)(Bg + (size_t)l_r0 * K + k0 + l_c0);
            pb1 = *(const uint4*)(Bg + (size_t)l_r1 * K + k0 + l_c1);
        }
#pragma unroll
        for (int ks = 0; ks < BK; ks += 16) {
            uint32_t af[4][4], bf[4][2];
#pragma unroll
            for (int mi = 0; mi < 4; mi++) {
                const int r = wm * 64 + mi * 16 + gid;
                af[mi][0] = *(const uint32_t*)&As[buf][r][ks + 2 * tig];
                af[mi][1] = *(const uint32_t*)&As[buf][r + 8][ks + 2 * tig];
                af[mi][2] = *(const uint32_t*)&As[buf][r][ks + 2 * tig + 8];
                af[mi][3] = *(const uint32_t*)&As[buf][r + 8][ks + 2 * tig + 8];
            }
#pragma unroll
            for (int ni = 0; ni < 4; ni++) {
                const int n = wn * 32 + ni * 8 + gid;
                bf[ni][0] = *(const uint32_t*)&Bs[buf][n][ks + 2 * tig];
                bf[ni][1] = *(const uint32_t*)&Bs[buf][n][ks + 2 * tig + 8];
            }
#pragma unroll
            for (int mi = 0; mi < 4; mi++)
#pragma unroll
                for (int ni = 0; ni < 4; ni++)
                    mma_f16(acc[mi][ni][0], acc[mi][ni][1], acc[mi][ni][2], acc[mi][ni][3],
                            af[mi][0], af[mi][1], af[mi][2], af[mi][3],
                            bf[ni][0], bf[ni][1]);
        }
        if (c + 1 < NCHUNK) {
            const int nb = buf ^ 1;
            *(uint4*)&As[nb][l_r0][l_c0] = pa0;
            *(uint4*)&As[nb][l_r1][l_c1] = pa1;
            *(uint4*)&Bs[nb][l_r0][l_c0] = pb0;
            *(uint4*)&Bs[nb][l_r1][l_c1] = pb1;
            __syncthreads();
            buf ^= 1;
        }
    }

    // epilogue: D row = gid (+8), col = 2*tig (+1); silu on z-half
    const bool is_z = (blockIdx.x >= (D_INNER / BN));
    float* Cb = g_xz + (size_t)row0 * N + col0;
#pragma unroll
    for (int mi = 0; mi < 4; mi++) {
#pragma unroll
        for (int ni = 0; ni < 4; ni++) {
            const int row = wm * 64 + mi * 16 + gid;
            const int col = wn * 32 + ni * 8 + 2 * tig;
            float v0 = acc[mi][ni][0], v1 = acc[mi][ni][1];
            float v2 = acc[mi][ni][2], v3 = acc[mi][ni][3];
            if (is_z) {
                v0 = v0 * __frcp_rn(1.0f + __expf(-v0));
                v1 = v1 * __frcp_rn(1.0f + __expf(-v1));
                v2 = v2 * __frcp_rn(1.0f + __expf(-v2));
                v3 = v3 * __frcp_rn(1.0f + __expf(-v3));
            }
            *(float2*)(Cb + (size_t)row * N + col) = make_float2(v0, v1);
            *(float2*)(Cb + (size_t)(row + 8) * N + col) = make_float2(v2, v3);
        }
    }
}

// ---------------------------------------------------------------------------
// K2: depthwise causal conv (K=4) + bias + SiLU -> u_c
// ---------------------------------------------------------------------------
__global__ __launch_bounds__(256) void conv_kernel(const float* __restrict__ W_conv,
                                                   const float* __restrict__ b_conv) {
    const int idx = blockIdx.x * 256 + threadIdx.x;
    const int d  = idx & (D_INNER - 1);
    const int bl = idx >> 9;
    const int l  = bl & (SEQ_LEN - 1);
    const int b  = bl >> 11;
    float acc = b_conv[d];
#pragma unroll
    for (int k = 0; k < KCONV; k++) {
        const int ll = l + k - (KCONV - 1);
        if (ll >= 0)
            acc = fmaf(g_xz[(size_t)(b * SEQ_LEN + ll) * (2 * D_INNER) + d],
                       W_conv[d * KCONV + k], acc);
    }
    g_uc[idx] = acc * __frcp_rn(1.0f + __expf(-acc));
}

// ---------------------------------------------------------------------------
// K3: x_dbl = u_c @ W_xproj (tf32 TC, 3-pass split — error ~1e-7)
// ---------------------------------------------------------------------------
__global__ __launch_bounds__(256) void xproj_tc_kernel(const float* __restrict__ W) {
    constexpr int K = D_INNER;
    constexpr int BM = 64, BN = 64, BK = 16;
    constexpr int NCHUNK = K / BK;
    constexpr int ASTR = BK + 4;
    constexpr int BSTR = BN + 8;
    __shared__ float As[2][BM][ASTR];
    __shared__ float Bs[2][BK][BSTR];

    const int tid  = threadIdx.x;
    const int warp = tid >> 5, lane = tid & 31;
    const int wm = warp & 1, wn = warp >> 1;
    const int gid = lane >> 2, tig = lane & 3;

    const float* Ab = g_uc + (size_t)blockIdx.x * BM * K;
    const int a_r = tid >> 2, a_c4 = (tid & 3) << 2;

    float acc[2][2][4];
#pragma unroll
    for (int mi = 0; mi < 2; mi++)
#pragma unroll
        for (int ni = 0; ni < 2; ni++)
#pragma unroll
            for (int q = 0; q < 4; q++) acc[mi][ni][q] = 0.f;

    {
        *(float4*)&As[0][a_r][a_c4] = *(const float4*)(Ab + a_r * K + a_c4);
#pragma unroll
        for (int s = 0; s < 4; s++) {
            const int i = tid + s * 256;
            const int kk = i >> 6, nn = i & 63;
            Bs[0][kk][nn] = (nn < XPROJ_N) ? W[kk * XPROJ_N + nn] : 0.f;
        }
    }
    __syncthreads();

    int buf = 0;
    for (int c = 0; c < NCHUNK; c++) {
        float4 pa;
        float pbv[4];
        if (c + 1 < NCHUNK) {
            const int k0 = (c + 1) * BK;
            pa = *(const float4*)(Ab + a_r * K + k0 + a_c4);
#pragma unroll
            for (int s = 0; s < 4; s++) {
                const int i = tid + s * 256;
                const int kk = i >> 6, nn = i & 63;
                pbv[s] = (nn < XPROJ_N) ? W[(k0 + kk) * XPROJ_N + nn] : 0.f;
            }
        }
#pragma unroll
        for (int ks = 0; ks < BK; ks += 8) {
            uint32_t ahi[2][4], alo[2][4], bhi[2][2], blo[2][2];
#pragma unroll
            for (int mi = 0; mi < 2; mi++) {
                const int r = wm * 32 + mi * 16 + gid;
                split_tf32(As[buf][r][ks + tig],         ahi[mi][0], alo[mi][0]);
                split_tf32(As[buf][r + 8][ks + tig],     ahi[mi][1], alo[mi][1]);
                split_tf32(As[buf][r][ks + tig + 4],     ahi[mi][2], alo[mi][2]);
                split_tf32(As[buf][r + 8][ks + tig + 4], ahi[mi][3], alo[mi][3]);
            }
#pragma unroll
            for (int ni = 0; ni < 2; ni++) {
                const int cc = wn * 16 + ni * 8 + gid;
                split_tf32(Bs[buf][ks + tig][cc],     bhi[ni][0], blo[ni][0]);
                split_tf32(Bs[buf][ks + tig + 4][cc], bhi[ni][1], blo[ni][1]);
            }
#pragma unroll
            for (int mi = 0; mi < 2; mi++)
#pragma unroll
                for (int ni = 0; ni < 2; ni++) {
                    mma_tf32(acc[mi][ni][0], acc[mi][ni][1], acc[mi][ni][2], acc[mi][ni][3],
                             ahi[mi][0], ahi[mi][1], ahi[mi][2], ahi[mi][3],
                             bhi[ni][0], bhi[ni][1]);
                    mma_tf32(acc[mi][ni][0], acc[mi][ni][1], acc[mi][ni][2], acc[mi][ni][3],
                             alo[mi][0], alo[mi][1], alo[mi][2], alo[mi][3],
                             bhi[ni][0], bhi[ni][1]);
                    mma_tf32(acc[mi][ni][0], acc[mi][ni][1], acc[mi][ni][2], acc[mi][ni][3],
                             ahi[mi][0], ahi[mi][1], ahi[mi][2], ahi[mi][3],
                             blo[ni][0], blo[ni][1]);
                }
        }
        if (c + 1 < NCHUNK) {
            const int nb = buf ^ 1;
            *(float4*)&As[nb][a_r][a_c4] = pa;
#pragma unroll
            for (int s = 0; s < 4; s++) {
                const int i = tid + s * 256;
                const int kk = i >> 6, nn = i & 63;
                Bs[nb][kk][nn] = pbv[s];
            }
            __syncthreads();
            buf ^= 1;
        }
    }

    const size_t row0 = (size_t)blockIdx.x * BM;
#pragma unroll
    for (int mi = 0; mi < 2; mi++) {
#pragma unroll
        for (int ni = 0; ni < 2; ni++) {
            const int row = wm * 32 + mi * 16 + gid;
            const int col = wn * 16 + ni * 8 + 2 * tig;
            if (col < XPROJ_N) {
                *(float2*)(g_xdbl + (row0 + row) * XPROJ_N + col) =
                    make_float2(acc[mi][ni][0], acc[mi][ni][1]);
                *(float2*)(g_xdbl + (row0 + row + 8) * XPROJ_N + col) =
                    make_float2(acc[mi][ni][2], acc[mi][ni][3]);
            }
        }
    }
}

// ---------------------------------------------------------------------------
// K4: SEGMENTED selective scan (CH=32, Bp/Cp transposed).
// ---------------------------------------------------------------------------
__global__ __launch_bounds__(256) void scan_seg_kernel(const float* __restrict__ A_log,
                                                       const float* __restrict__ W_dt,
                                                       const float* __restrict__ b_dt) {
    constexpr int CH = 32;
    constexpr int PW = 36;
    __shared__ float w_s[16][PW];
    __shared__ float wu_s[16][PW];
    __shared__ float g_s[16][PW];
    __shared__ float bp_s[16][PW];
    __shared__ float cp_s[16][PW];
    __shared__ float xd_s[CH * XPROJ_N];
    __shared__ float Wdt_s[DT_RANK][16];
    __shared__ float bdt_s[16];
    __shared__ float accD_red[16][16];

    const int tid = threadIdx.x;
    const int gi = tid >> 4;
    const int n  = tid & 15;
    const int blk  = blockIdx.x;
    const int dgrp = blk & 31;
    const int s    = (blk >> 5) & (SEGS - 1);
    const int b    = blk >> 9;
    const int d0 = dgrp * 16;
    const int d  = d0 + gi;
    const int l_base = s * SEG_LEN;

    const int p_dd = tid & 15;
    const int p_li = tid >> 4;

    if (tid < DT_RANK * 16)
        Wdt_s[tid >> 4][tid & 15] = W_dt[(tid >> 4) * D_INNER + d0 + (tid & 15)];
    if (tid < 16) bdt_s[tid] = b_dt[d0 + tid];

    const float A_n = -__expf(A_log[d * D_STATE + n]);

    float h = 0.f, P = 1.f, acc = 0.f, coef = 0.f, accD_th = 0.f;

    for (int l0 = l_base; l0 < l_base + SEG_LEN; l0 += CH) {
        __syncthreads();
        const size_t bl0 = (size_t)(b * SEQ_LEN + l0);
        {
            const int dd = tid & 15, li0 = tid >> 4;
#pragma unroll
            for (int q = 0; q < 2; q++) {
                const int li = li0 + q * 16;
                const size_t bl = bl0 + li;
                wu_s[dd][li] = g_uc[bl * D_INNER + d0 + dd];
                g_s[dd][li]  = g_xz[bl * (2 * D_INNER) + D_INNER + d0 + dd];
            }
        }
#pragma unroll
        for (int q = 0; q < 6; q++) {
            const int i = tid + q * 256;
            if (i < CH * XPROJ_N) xd_s[i] = g_xdbl[bl0 * XPROJ_N + i];
        }
        __syncthreads();
#pragma unroll
        for (int q = 0; q < 2; q++) {
            const int li = p_li + q * 16;
            float dtr = bdt_s[p_dd];
#pragma unroll
            for (int r = 0; r < DT_RANK; r++)
                dtr = fmaf(xd_s[li * XPROJ_N + r], Wdt_s[r][p_dd], dtr);
            const float w = (dtr > 15.0f) ? dtr : log1pf(__expf(dtr));
            const float u = wu_s[p_dd][li];
            const float gate = g_s[p_dd][li];
            w_s[p_dd][li]  = w;
            wu_s[p_dd][li] = w * u;
            accD_th = fmaf(gate, u, accD_th);
            bp_s[p_dd][li] = xd_s[li * XPROJ_N + DT_RANK + p_dd];
            cp_s[p_dd][li] = xd_s[li * XPROJ_N + DT_RANK + D_STATE + p_dd];
        }
        __syncthreads();
#pragma unroll
        for (int l4 = 0; l4 < CH; l4 += 4) {
            const float4 w4  = *(const float4*)&w_s[gi][l4];
            const float4 wu4 = *(const float4*)&wu_s[gi][l4];
            const float4 g4  = *(const float4*)&g_s[gi][l4];
            const float4 bp4 = *(const float4*)&bp_s[n][l4];
            const float4 cp4 = *(const float4*)&cp_s[n][l4];
#pragma unroll
            for (int q = 0; q < 4; q++) {
                const float w  = (q == 0) ? w4.x  : (q == 1) ? w4.y  : (q == 2) ? w4.z  : w4.w;
                const float wu = (q == 0) ? wu4.x : (q == 1) ? wu4.y : (q == 2) ? wu4.z : wu4.w;
                const float gt = (q == 0) ? g4.x  : (q == 1) ? g4.y  : (q == 2) ? g4.z  : g4.w;
                const float bn = (q == 0) ? bp4.x : (q == 1) ? bp4.y : (q == 2) ? bp4.z : bp4.w;
                const float cn = (q == 0) ? cp4.x : (q == 1) ? cp4.y : (q == 2) ? cp4.z : cp4.w;
                const float dA = __expf(w * A_n);
                P *= dA;
                h = fmaf(dA, h, wu * bn);
                const float gc = gt * cn;
                acc  = fmaf(gc, h, acc);
                coef = fmaf(gc, P, coef);
            }
        }
    }
    const size_t base = ((size_t)(b * SEGS + s) * D_INNER + d0) * D_STATE + tid;
    g_seg[base] = make_float4(acc, coef, P, h);
    accD_red[p_li][p_dd] = accD_th;
    __syncthreads();
    if (n == 0) {
        float accD = 0.f;
#pragma unroll
        for (int g = 0; g < 16; g++) accD += accD_red[g][gi];
        g_accD[(size_t)(b * SEGS + s) * D_INNER + d] = accD;
    }
}

// ---------------------------------------------------------------------------
// K5: fixup — prefetch all 16 segment summaries (MLP), then combine.
// ---------------------------------------------------------------------------
__global__ __launch_bounds__(256) void scan_fix_kernel(const float* __restrict__ Dp) {
    const int idx = blockIdx.x * 256 + threadIdx.x;
    const int n = idx & 15;
    const int d = (idx >> 4) & (D_INNER - 1);
    const int b = idx >> 13;

    float4 sg[SEGS];
#pragma unroll
    for (int s = 0; s < SEGS; s++)
        sg[s] = g_seg[((size_t)(b * SEGS + s) * D_INNER + d) * D_STATE + n];

    float accD = 0.f;
    if (n == 0) {
#pragma unroll
        for (int s = 0; s < SEGS; s++)
            accD += g_accD[(size_t)(b * SEGS + s) * D_INNER + d];
    }

    float carry = 0.f, accT = 0.f;
#pragma unroll
    for (int s = 0; s < SEGS; s++) {
        accT  = accT + sg[s].x + sg[s].y * carry;
        carry = fmaf(sg[s].z, carry, sg[s].w);
    }
#pragma unroll
    for (int off = 8; off >= 1; off >>= 1)
        accT += __shfl_xor_sync(0xffffffffu, accT, off);
    if (n == 0)
        g_pooled[b * D_INNER + d] = (accT + Dp[d] * accD) * (1.0f / SEQ_LEN);
}

// ---------------------------------------------------------------------------
// K6: logits = (pooled @ W_out) @ W_cls + b_cls
// ---------------------------------------------------------------------------
__global__ __launch_bounds__(256) void final_kernel(const float* __restrict__ W_out,
                                                    const float* __restrict__ W_cls,
                                                    const float* __restrict__ b_cls,
                                                    float* __restrict__ out) {
    __shared__ float p_s[B_SZ * D_INNER];
    __shared__ float t_s[B_SZ * D_MODEL];
    const int tid = threadIdx.x;
    for (int i = tid; i < B_SZ * D_INNER; i += 256) p_s[i] = g_pooled[i];
    __syncthreads();
    float a0 = 0.f, a1 = 0.f, a2 = 0.f, a3 = 0.f;
#pragma unroll 8
    for (int k = 0; k < D_INNER; k++) {
        const float w = W_out[k * D_MODEL + tid];
        a0 = fmaf(p_s[k], w, a0);
        a1 = fmaf(p_s[D_INNER + k], w, a1);
        a2 = fmaf(p_s[2 * D_INNER + k], w, a2);
        a3 = fmaf(p_s[3 * D_INNER + k], w, a3);
    }
    t_s[tid] = a0; t_s[D_MODEL + tid] = a1;
    t_s[2 * D_MODEL + tid] = a2; t_s[3 * D_MODEL + tid] = a3;
    __syncthreads();
    if (tid < B_SZ * N_CLS) {
        const int bb = tid / N_CLS, c = tid % N_CLS;
        float acc = b_cls[c];
        for (int k = 0; k < D_MODEL; k++)
            acc = fmaf(t_s[bb * D_MODEL + k], W_cls[k * N_CLS + c], acc);
        out[tid] = acc;
    }
}

// ---------------------------------------------------------------------------
extern "C" void kernel_launch(void* const* d_in, const int* in_sizes, int n_in,
                              void* d_out, int out_size) {
    const float* x       = (const float*)d_in[0];
    const float* W_in    = (const float*)d_in[1];
    const float* W_conv  = (const float*)d_in[2];
    const float* b_conv  = (const float*)d_in[3];
    const float* W_xproj = (const float*)d_in[4];
    const float* W_dt    = (const float*)d_in[5];
    const float* b_dt    = (const float*)d_in[6];
    const float* A_log   = (const float*)d_in[7];
    const float* Dp      = (const float*)d_in[8];
    const float* W_out   = (const float*)d_in[9];
    const float* W_cls   = (const float*)d_in[10];
    const float* b_cls   = (const float*)d_in[11];
    float* out = (float*)d_out;

    cvt_x_kernel<<<BL * D_MODEL / 1024, 256>>>(x);
    cvt_wT_kernel<<<dim3(D_MODEL / 32, 2 * D_INNER / 32), 256>>>(W_in);
    gemm1_f16_kernel<<<dim3(2 * D_INNER / 128, BL / 128), 256>>>();
    conv_kernel<<<BL * D_INNER / 256, 256>>>(W_conv, b_conv);
    xproj_tc_kernel<<<BL / 64, 256>>>(W_xproj);
    scan_seg_kernel<<<B_SZ * SEGS * (D_INNER / 16), 256>>>(A_log, W_dt, b_dt);
    scan_fix_kernel<<<B_SZ * D_INNER * D_STATE / 256, 256>>>(Dp);
    final_kernel<<<1, 256>>>(W_out, W_cls, b_cls, out);
}